// round 1
// baseline (speedup 1.0000x reference)
#include <cuda_runtime.h>
#include <cstdint>

// OverlapPatchEmbed: extract overlapping 16x16 patches with stride 8 from
// x (64, 3, 224, 224) fp32 -> out (64, 729, 3, 256) fp32.
//
// Pure gather. One thread per output float4 (4 consecutive kx values).
// Output stores fully coalesced; input loads are 16B-aligned contiguous
// 4-float chunks (col = px*8 + 4*j, row stride 224 floats = 896 B, both
// multiples of 16 B). Input (38.5 MB) fits in L2, so the ~4x read
// replication is absorbed by L2; HBM traffic ~= 38.5 MB read + 143 MB write.

static constexpr int B  = 64;
static constexpr int C  = 3;
static constexpr int H  = 224;
static constexpr int W  = 224;
static constexpr int P  = 16;   // patch_size
static constexpr int S  = 8;    // stride = patch_size - overlap
static constexpr int N  = 27;   // patches per dim
static constexpr int NN = N * N;            // 729
static constexpr int KK = P * P;            // 256 elements per patch per channel
static constexpr int OUT_ELEMS = B * NN * C * KK;   // 35,831,808
static constexpr int OUT_VEC4  = OUT_ELEMS / 4;     // 8,957,952

__global__ void overlap_patch_kernel(const float* __restrict__ x,
                                     float* __restrict__ out)
{
    int64_t i = (int64_t)blockIdx.x * blockDim.x + threadIdx.x;
    if (i >= OUT_VEC4) return;

    // Decompose output float4 index:
    // layout (b, py, px, c, ky, kx4) with kx4 in [0,4) selecting 4 floats.
    int kx4 = (int)(i & 3);             // 4 float4 per 16-wide row
    int t   = (int)(i >> 2);
    int ky  = t & 15;                   // 16 rows per patch
    t >>= 4;
    int c   = t % C;
    t /= C;
    int px  = t % N;
    t /= N;
    int py  = t % N;
    int b   = t / N;

    int row = py * S + ky;              // input row
    int col = px * S + kx4 * 4;         // input col (16B aligned)

    const float4* src = reinterpret_cast<const float4*>(
        x + (((int64_t)b * C + c) * H + row) * W + col);

    float4 v = *src;

    reinterpret_cast<float4*>(out)[i] = v;
}

extern "C" void kernel_launch(void* const* d_in, const int* in_sizes, int n_in,
                              void* d_out, int out_size)
{
    const float* x = (const float*)d_in[0];
    float* out = (float*)d_out;

    int threads = 256;
    int blocks = (OUT_VEC4 + threads - 1) / threads;
    overlap_patch_kernel<<<blocks, threads>>>(x, out);
}